// round 3
// baseline (speedup 1.0000x reference)
#include <cuda_runtime.h>
#include <cuda_bf16.h>
#include <cstdint>

#define T_SEQ 512
#define DIN   32
#define HDIM  64
#define G     256     // 4*H gate rows
#define NB    8       // batches per CTA
#define NBH   4       // batches per thread (half)
#define NTHR  512
#define SW0_S 68      // Whh0 row stride (floats): 68/4=17 odd -> conflict-free LDS.128
#define SW1_S 132     // [Wih1|Whh1] row stride: 132/4=33 odd -> conflict-free
#define ZB_S  9       // gate-exchange stride: 9 coprime 32 -> conflict-free scalar

// smem floats:
//   sW0: 256*68 =17408 | sW1: 256*132=33792 | zb: 256*9=2304
//   in0: 8*96 = 768 (x|h0) | in1: 8*128 = 1024 (h0|h1)
#define SMEM_FLOATS (G*SW0_S + G*SW1_S + G*ZB_S + NB*96 + NB*128)

__device__ __forceinline__ unsigned long long pack2(float lo, float hi) {
    unsigned long long r;
    asm("mov.b64 %0, {%1,%2};" : "=l"(r) : "f"(lo), "f"(hi));
    return r;
}
__device__ __forceinline__ void fma2(unsigned long long& d,
                                     unsigned long long a, unsigned long long b) {
    asm("fma.rn.f32x2 %0, %1, %2, %0;" : "+l"(d) : "l"(a), "l"(b));
}
__device__ __forceinline__ float hsum2(unsigned long long v) {
    float lo, hi;
    asm("mov.b64 {%0,%1}, %2;" : "=f"(lo), "=f"(hi) : "l"(v));
    return lo + hi;
}
__device__ __forceinline__ float sigmoid_fast(float x) {
    return __fdividef(1.0f, 1.0f + __expf(-x));
}
__device__ __forceinline__ float tanh_fast(float x) {
    // 1 - 2/(exp(2x)+1): correct saturation both directions
    return 1.0f - __fdividef(2.0f, __expf(2.0f * x) + 1.0f);
}

extern __shared__ float smem[];

__global__ void __launch_bounds__(NTHR, 1)
lstm_return_kernel(const float* __restrict__ x,
                   const float* __restrict__ Wih0, const float* __restrict__ Whh0,
                   const float* __restrict__ bih0, const float* __restrict__ bhh0,
                   const float* __restrict__ Wih1, const float* __restrict__ Whh1,
                   const float* __restrict__ bih1, const float* __restrict__ bhh1,
                   const float* __restrict__ W1,   const float* __restrict__ b1,
                   const float* __restrict__ W2,   const float* __restrict__ b2,
                   float* __restrict__ out)
{
    float* sW0 = smem;                 // [256][68]  Whh0
    float* sW1 = sW0 + G * SW0_S;      // [256][132] [Wih1|Whh1]
    float* zb  = sW1 + G * SW1_S;      // [256][9]   activated gates
    float* in0 = zb  + G * ZB_S;       // [8][96]    x(0:32) | h0(32:96)
    float* in1 = in0 + NB * 96;        // [8][128]   h0(0:64) | h1(64:128)

    const int tid   = threadIdx.x;
    const int j     = tid & 255;       // gate row
    const int bh    = tid >> 8;        // batch half (0/1)
    const int bb    = bh * NBH;        // first batch of this half
    const int bbase = blockIdx.x * NB;

    // ---- stage weights into smem ----
    for (int i = tid; i < G * HDIM; i += NTHR) {
        int r = i >> 6, c = i & 63;
        sW0[r * SW0_S + c]        = Whh0[i];
        sW1[r * SW1_S + c]        = Wih1[i];
        sW1[r * SW1_S + HDIM + c] = Whh1[i];
    }
    for (int i = tid; i < NB * 96;  i += NTHR) in0[i] = 0.0f;
    for (int i = tid; i < NB * 128; i += NTHR) in1[i] = 0.0f;

    // ---- x-path weights (row j of Wih0) in registers, packed f32x2 ----
    unsigned long long wxp[16];
#pragma unroll
    for (int k = 0; k < 16; k++)
        wxp[k] = pack2(Wih0[j * DIN + 2 * k], Wih0[j * DIN + 2 * k + 1]);

    const float bsum0 = bih0[j] + bhh0[j];
    const float bsum1 = bih1[j] + bhh1[j];
    const bool  row_is_tanh = ((j >> 6) == 2);   // g-gate rows

    // cell-state owner mapping: one (unit, batch) pair per thread per layer
    const int cu = tid & 63;          // unit 0..63
    const int cb = tid >> 6;          // batch 0..7
    float c0 = 0.f, c1 = 0.f;

    // x prefetch: first 256 threads -> (batch xb, channel xk), coalesced rows
    const int xb = (tid >> 5) & 7, xk = tid & 31;
    const float* xptr = x + ((size_t)(bbase + xb) * T_SEQ) * DIN + xk;
    float xreg = (tid < 256) ? xptr[0] : 0.0f;

    const float* w0row = sW0 + j * SW0_S;
    const float* w1row = sW1 + j * SW1_S;

    __syncthreads();

    for (int t = 0; t < T_SEQ; t++) {
        // stage x(t); prefetch x(t+1)
        if (tid < 256) {
            in0[xb * 96 + xk] = xreg;
            if (t + 1 < T_SEQ) xreg = xptr[(t + 1) * DIN];
        }
        __syncthreads();                                  // (A)

        // ===== layer 0 gates: z0 = x@Wih0^T + h0@Whh0^T + bias =====
        {
            unsigned long long acc[NBH];
#pragma unroll
            for (int b = 0; b < NBH; b++) acc[b] = pack2(bsum0, 0.0f);

            // x part: weights in regs, inputs broadcast LDS.128
#pragma unroll
            for (int kc = 0; kc < 8; kc++) {
                const unsigned long long w0 = wxp[2 * kc], w1 = wxp[2 * kc + 1];
#pragma unroll
                for (int b = 0; b < NBH; b++) {
                    ulonglong2 iv = *(const ulonglong2*)(in0 + (bb + b) * 96 + 4 * kc);
                    fma2(acc[b], w0, iv.x);
                    fma2(acc[b], w1, iv.y);
                }
            }
            // h part: weights LDS.128 (conflict-free pad-68), inputs broadcast
#pragma unroll
            for (int kc = 0; kc < 16; kc++) {
                ulonglong2 wv = *(const ulonglong2*)(w0row + 4 * kc);
#pragma unroll
                for (int b = 0; b < NBH; b++) {
                    ulonglong2 iv = *(const ulonglong2*)(in0 + (bb + b) * 96 + 32 + 4 * kc);
                    fma2(acc[b], wv.x, iv.x);
                    fma2(acc[b], wv.y, iv.y);
                }
            }
#pragma unroll
            for (int b = 0; b < NBH; b++) {
                float z = hsum2(acc[b]);
                zb[j * ZB_S + bb + b] = row_is_tanh ? tanh_fast(z) : sigmoid_fast(z);
            }
        }
        __syncthreads();                                  // (B)

        // ===== layer 0 cell update: one (unit, batch) pair per thread =====
        {
            const float* zc = zb + cu * ZB_S;
            float i_ = zc[0 * 64 * ZB_S + cb];
            float f_ = zc[1 * 64 * ZB_S + cb];
            float g_ = zc[2 * 64 * ZB_S + cb];
            float o_ = zc[3 * 64 * ZB_S + cb];
            c0 = f_ * c0 + i_ * g_;
            float h = o_ * tanh_fast(c0);
            in0[cb * 96 + 32 + cu] = h;
            in1[cb * 128 + cu]     = h;
        }
        __syncthreads();                                  // (C)

        // ===== layer 1 gates: z1 = [h0|h1] @ [Wih1|Whh1]^T + bias =====
        {
            unsigned long long acc[NBH];
#pragma unroll
            for (int b = 0; b < NBH; b++) acc[b] = pack2(bsum1, 0.0f);
#pragma unroll
            for (int kc = 0; kc < 32; kc++) {
                ulonglong2 wv = *(const ulonglong2*)(w1row + 4 * kc);
#pragma unroll
                for (int b = 0; b < NBH; b++) {
                    ulonglong2 iv = *(const ulonglong2*)(in1 + (bb + b) * 128 + 4 * kc);
                    fma2(acc[b], wv.x, iv.x);
                    fma2(acc[b], wv.y, iv.y);
                }
            }
#pragma unroll
            for (int b = 0; b < NBH; b++) {
                float z = hsum2(acc[b]);
                zb[j * ZB_S + bb + b] = row_is_tanh ? tanh_fast(z) : sigmoid_fast(z);
            }
        }
        __syncthreads();                                  // (D)

        // ===== layer 1 cell update =====
        {
            const float* zc = zb + cu * ZB_S;
            float i_ = zc[0 * 64 * ZB_S + cb];
            float f_ = zc[1 * 64 * ZB_S + cb];
            float g_ = zc[2 * 64 * ZB_S + cb];
            float o_ = zc[3 * 64 * ZB_S + cb];
            c1 = f_ * c1 + i_ * g_;
            in1[cb * 128 + 64 + cu] = o_ * tanh_fast(c1);
        }
        // no sync needed here: (A) next iteration orders zb/in1 reuse
    }

    __syncthreads();   // final h1 visible to head

    // ===== head: out = relu(h1 @ W1^T + b1) @ W2^T + b2 =====
    if (tid < 256) {
        const int hb = tid >> 5;    // batch 0..7
        const int hu = tid & 31;    // hidden unit 0..31
        const float* w1r = W1 + hu * HDIM;
        const float* hv  = in1 + hb * 128 + 64;
        float acc = b1[hu];
#pragma unroll
        for (int k = 0; k < HDIM; k++) acc += w1r[k] * hv[k];
        acc = fmaxf(acc, 0.0f) * W2[hu];
        zb[hb * 32 + hu] = acc;     // reuse zb as scratch
    }
    __syncthreads();
    if (tid < NB) {
        float s = b2[0];
#pragma unroll
        for (int u = 0; u < 32; u++) s += zb[tid * 32 + u];
        out[bbase + tid] = s;
    }
}

extern "C" void kernel_launch(void* const* d_in, const int* in_sizes, int n_in,
                              void* d_out, int out_size) {
    (void)in_sizes; (void)n_in; (void)out_size;
    const float* x    = (const float*)d_in[0];
    const float* Wih0 = (const float*)d_in[1];
    const float* Whh0 = (const float*)d_in[2];
    const float* bih0 = (const float*)d_in[3];
    const float* bhh0 = (const float*)d_in[4];
    const float* Wih1 = (const float*)d_in[5];
    const float* Whh1 = (const float*)d_in[6];
    const float* bih1 = (const float*)d_in[7];
    const float* bhh1 = (const float*)d_in[8];
    const float* W1   = (const float*)d_in[9];
    const float* b1   = (const float*)d_in[10];
    const float* W2   = (const float*)d_in[11];
    const float* b2   = (const float*)d_in[12];
    float* out = (float*)d_out;

    const size_t smem_bytes = (size_t)SMEM_FLOATS * sizeof(float);
    cudaFuncSetAttribute(lstm_return_kernel,
                         cudaFuncAttributeMaxDynamicSharedMemorySize,
                         (int)smem_bytes);
    lstm_return_kernel<<<1024 / NB, NTHR, smem_bytes>>>(
        x, Wih0, Whh0, bih0, bhh0, Wih1, Whh1, bih1, bhh1,
        W1, b1, W2, b2, out);
}

// round 4
// speedup vs baseline: 1.0961x; 1.0961x over previous
#include <cuda_runtime.h>
#include <cuda_bf16.h>
#include <cstdint>

#define T_SEQ 512
#define DIN   32
#define HDIM  64
#define G     256     // 4*H gate rows
#define NB    8       // batches per CTA
#define NTHR  256
#define SW1_S 132     // [Wih1|Whh1] row stride: 132/4=33 odd -> conflict-free LDS.128
#define ZB_S  9       // gate-exchange stride: 9 coprime 32 -> conflict-free scalar

// smem floats:
//   sW1: 256*132=33792 | zb: 256*9=2304 | in0: 8*96=768 | in1: 8*128=1024
#define SMEM_FLOATS (G*SW1_S + G*ZB_S + NB*96 + NB*128)

__device__ __forceinline__ unsigned long long pack2(float lo, float hi) {
    unsigned long long r;
    asm("mov.b64 %0, {%1,%2};" : "=l"(r) : "f"(lo), "f"(hi));
    return r;
}
__device__ __forceinline__ void fma2(unsigned long long& d,
                                     unsigned long long a, unsigned long long b) {
    asm("fma.rn.f32x2 %0, %1, %2, %0;" : "+l"(d) : "l"(a), "l"(b));
}
__device__ __forceinline__ float hsum2(unsigned long long v) {
    float lo, hi;
    asm("mov.b64 {%0,%1}, %2;" : "=f"(lo), "=f"(hi) : "l"(v));
    return lo + hi;
}
__device__ __forceinline__ float sigmoid_fast(float x) {
    return __fdividef(1.0f, 1.0f + __expf(-x));
}
__device__ __forceinline__ float tanh_fast(float x) {
    return 1.0f - __fdividef(2.0f, __expf(2.0f * x) + 1.0f);
}

extern __shared__ float smem[];

__global__ void __launch_bounds__(NTHR, 1)
lstm_return_kernel(const float* __restrict__ x,
                   const float* __restrict__ Wih0, const float* __restrict__ Whh0,
                   const float* __restrict__ bih0, const float* __restrict__ bhh0,
                   const float* __restrict__ Wih1, const float* __restrict__ Whh1,
                   const float* __restrict__ bih1, const float* __restrict__ bhh1,
                   const float* __restrict__ W1,   const float* __restrict__ b1,
                   const float* __restrict__ W2,   const float* __restrict__ b2,
                   float* __restrict__ out)
{
    float* sW1 = smem;                 // [256][132] [Wih1|Whh1]
    float* zb  = sW1 + G * SW1_S;      // [256][9]   activated gates
    float* in0 = zb  + G * ZB_S;       // [8][96]    x(0:32) | h0(32:96)
    float* in1 = in0 + NB * 96;        // [8][128]   h0(0:64) | h1(64:128)

    const int tid   = threadIdx.x;
    const int j     = tid;             // gate row owned by this thread
    const int bbase = blockIdx.x * NB;

    // ---- stage layer-1 weights into smem ----
    for (int i = tid; i < G * HDIM; i += NTHR) {
        int r = i >> 6, c = i & 63;
        sW1[r * SW1_S + c]        = Wih1[i];
        sW1[r * SW1_S + HDIM + c] = Whh1[i];
    }
    for (int i = tid; i < NB * 96;  i += NTHR) in0[i] = 0.0f;
    for (int i = tid; i < NB * 128; i += NTHR) in1[i] = 0.0f;

    // ---- layer-0 weights (row j) entirely in registers, packed f32x2 ----
    unsigned long long wxp[16];   // Wih0 row (32 floats)
#pragma unroll
    for (int k = 0; k < 16; k++)
        wxp[k] = pack2(Wih0[j * DIN + 2 * k], Wih0[j * DIN + 2 * k + 1]);
    unsigned long long whp[32];   // Whh0 row (64 floats)
#pragma unroll
    for (int k = 0; k < 32; k++)
        whp[k] = pack2(Whh0[j * HDIM + 2 * k], Whh0[j * HDIM + 2 * k + 1]);

    const float bsum0 = bih0[j] + bhh0[j];
    const float bsum1 = bih1[j] + bhh1[j];
    const bool  row_is_tanh = ((j >> 6) == 2);   // g-gate rows

    // cell-state owner: (unit cu, batches cb and cb+4)
    const int cu = tid & 63;
    const int cb = tid >> 6;          // 0..3
    float c0a = 0.f, c0b = 0.f, c1a = 0.f, c1b = 0.f;

    // x prefetch: thread -> (batch xb, channel xk), coalesced 128B rows
    const int xb = tid >> 5, xk = tid & 31;
    const float* xptr = x + ((size_t)(bbase + xb) * T_SEQ) * DIN + xk;
    float xreg = xptr[0];

    const float* w1row = sW1 + j * SW1_S;

    __syncthreads();

    for (int t = 0; t < T_SEQ; t++) {
        in0[xb * 96 + xk] = xreg;
        if (t + 1 < T_SEQ) xreg = xptr[(t + 1) * DIN];
        __syncthreads();                                  // (A)

        // ===== layer 0 gates: all weights in registers =====
        {
            unsigned long long acc[NB];
#pragma unroll
            for (int b = 0; b < NB; b++) acc[b] = pack2(bsum0, 0.0f);

            // x part
#pragma unroll
            for (int kc = 0; kc < 8; kc++) {
                const unsigned long long w0 = wxp[2 * kc], w1 = wxp[2 * kc + 1];
#pragma unroll
                for (int b = 0; b < NB; b++) {
                    ulonglong2 iv = *(const ulonglong2*)(in0 + b * 96 + 4 * kc);
                    fma2(acc[b], w0, iv.x);
                    fma2(acc[b], w1, iv.y);
                }
            }
            // h part (register weights)
#pragma unroll
            for (int kc = 0; kc < 16; kc++) {
                const unsigned long long w0 = whp[2 * kc], w1 = whp[2 * kc + 1];
#pragma unroll
                for (int b = 0; b < NB; b++) {
                    ulonglong2 iv = *(const ulonglong2*)(in0 + b * 96 + 32 + 4 * kc);
                    fma2(acc[b], w0, iv.x);
                    fma2(acc[b], w1, iv.y);
                }
            }
#pragma unroll
            for (int b = 0; b < NB; b++) {
                float z = hsum2(acc[b]);
                zb[j * ZB_S + b] = row_is_tanh ? tanh_fast(z) : sigmoid_fast(z);
            }
        }
        __syncthreads();                                  // (B)

        // ===== layer 0 cell update: (cu, cb) and (cu, cb+4) =====
        {
            const float* zc = zb + cu * ZB_S;
            {
                float i_ = zc[0 * 64 * ZB_S + cb];
                float f_ = zc[1 * 64 * ZB_S + cb];
                float g_ = zc[2 * 64 * ZB_S + cb];
                float o_ = zc[3 * 64 * ZB_S + cb];
                c0a = f_ * c0a + i_ * g_;
                float h = o_ * tanh_fast(c0a);
                in0[cb * 96 + 32 + cu] = h;
                in1[cb * 128 + cu]     = h;
            }
            {
                int b2i = cb + 4;
                float i_ = zc[0 * 64 * ZB_S + b2i];
                float f_ = zc[1 * 64 * ZB_S + b2i];
                float g_ = zc[2 * 64 * ZB_S + b2i];
                float o_ = zc[3 * 64 * ZB_S + b2i];
                c0b = f_ * c0b + i_ * g_;
                float h = o_ * tanh_fast(c0b);
                in0[b2i * 96 + 32 + cu] = h;
                in1[b2i * 128 + cu]     = h;
            }
        }
        __syncthreads();                                  // (C)

        // ===== layer 1 gates: weights from smem (pad-132, conflict-free) =====
        {
            unsigned long long acc[NB];
#pragma unroll
            for (int b = 0; b < NB; b++) acc[b] = pack2(bsum1, 0.0f);
#pragma unroll
            for (int kc = 0; kc < 32; kc++) {
                ulonglong2 wv = *(const ulonglong2*)(w1row + 4 * kc);
#pragma unroll
                for (int b = 0; b < NB; b++) {
                    ulonglong2 iv = *(const ulonglong2*)(in1 + b * 128 + 4 * kc);
                    fma2(acc[b], wv.x, iv.x);
                    fma2(acc[b], wv.y, iv.y);
                }
            }
#pragma unroll
            for (int b = 0; b < NB; b++) {
                float z = hsum2(acc[b]);
                zb[j * ZB_S + b] = row_is_tanh ? tanh_fast(z) : sigmoid_fast(z);
            }
        }
        __syncthreads();                                  // (D)

        // ===== layer 1 cell update =====
        {
            const float* zc = zb + cu * ZB_S;
            {
                float i_ = zc[0 * 64 * ZB_S + cb];
                float f_ = zc[1 * 64 * ZB_S + cb];
                float g_ = zc[2 * 64 * ZB_S + cb];
                float o_ = zc[3 * 64 * ZB_S + cb];
                c1a = f_ * c1a + i_ * g_;
                in1[cb * 128 + 64 + cu] = o_ * tanh_fast(c1a);
            }
            {
                int b2i = cb + 4;
                float i_ = zc[0 * 64 * ZB_S + b2i];
                float f_ = zc[1 * 64 * ZB_S + b2i];
                float g_ = zc[2 * 64 * ZB_S + b2i];
                float o_ = zc[3 * 64 * ZB_S + b2i];
                c1b = f_ * c1b + i_ * g_;
                in1[b2i * 128 + 64 + cu] = o_ * tanh_fast(c1b);
            }
        }
        // next (A) orders zb/in1 reuse
    }

    __syncthreads();

    // ===== head: out = relu(h1 @ W1^T + b1) @ W2^T + b2 =====
    {
        const int hb = tid >> 5;
        const int hu = tid & 31;
        const float* w1r = W1 + hu * HDIM;
        const float* hv  = in1 + hb * 128 + 64;
        float acc = b1[hu];
#pragma unroll
        for (int k = 0; k < HDIM; k++) acc += w1r[k] * hv[k];
        acc = fmaxf(acc, 0.0f) * W2[hu];
        zb[hb * 32 + hu] = acc;
    }
    __syncthreads();
    if (tid < NB) {
        float s = b2[0];
#pragma unroll
        for (int u = 0; u < 32; u++) s += zb[tid * 32 + u];
        out[bbase + tid] = s;
    }
}

extern "C" void kernel_launch(void* const* d_in, const int* in_sizes, int n_in,
                              void* d_out, int out_size) {
    (void)in_sizes; (void)n_in; (void)out_size;
    const float* x    = (const float*)d_in[0];
    const float* Wih0 = (const float*)d_in[1];
    const float* Whh0 = (const float*)d_in[2];
    const float* bih0 = (const float*)d_in[3];
    const float* bhh0 = (const float*)d_in[4];
    const float* Wih1 = (const float*)d_in[5];
    const float* Whh1 = (const float*)d_in[6];
    const float* bih1 = (const float*)d_in[7];
    const float* bhh1 = (const float*)d_in[8];
    const float* W1   = (const float*)d_in[9];
    const float* b1   = (const float*)d_in[10];
    const float* W2   = (const float*)d_in[11];
    const float* b2   = (const float*)d_in[12];
    float* out = (float*)d_out;

    const size_t smem_bytes = (size_t)SMEM_FLOATS * sizeof(float);
    cudaFuncSetAttribute(lstm_return_kernel,
                         cudaFuncAttributeMaxDynamicSharedMemorySize,
                         (int)smem_bytes);
    lstm_return_kernel<<<1024 / NB, NTHR, smem_bytes>>>(
        x, Wih0, Whh0, bih0, bhh0, Wih1, Whh1, bih1, bhh1,
        W1, b1, W2, b2, out);
}

// round 5
// speedup vs baseline: 1.1429x; 1.0427x over previous
#include <cuda_runtime.h>
#include <cuda_bf16.h>
#include <cstdint>

#define T_SEQ 512
#define DIN   32
#define HDIM  64
#define G     256     // 4*H gate rows
#define NB    8       // batches per CTA
#define NTHR  512     // 8 warps layer-0 (A) + 8 warps layer-1 (B)
#define SW0_S 68      // Whh0 row stride: 68/4=17 odd -> conflict-free LDS.128
#define SW1_S 132     // [Wih1|Whh1] row stride: 33 odd -> conflict-free
#define ZB_S  9       // gate-exchange stride: coprime 32 -> conflict-free scalar

// smem floats:
//   sW0: 256*68=17408 | sW1: 256*132=33792 | zb0: 2304 | zb1: 2304
//   in0: 8*96=768 (x|h0) | in1: 8*128=1024 (h0|h1)     total 57600 fl = 230400 B
#define SMEM_FLOATS (G*SW0_S + G*SW1_S + 2*(G*ZB_S) + NB*96 + NB*128)

__device__ __forceinline__ unsigned long long pack2(float lo, float hi) {
    unsigned long long r;
    asm("mov.b64 %0, {%1,%2};" : "=l"(r) : "f"(lo), "f"(hi));
    return r;
}
__device__ __forceinline__ void fma2(unsigned long long& d,
                                     unsigned long long a, unsigned long long b) {
    asm("fma.rn.f32x2 %0, %1, %2, %0;" : "+l"(d) : "l"(a), "l"(b));
}
__device__ __forceinline__ float hsum2(unsigned long long v) {
    float lo, hi;
    asm("mov.b64 {%0,%1}, %2;" : "=f"(lo), "=f"(hi) : "l"(v));
    return lo + hi;
}
__device__ __forceinline__ float sigmoid_fast(float x) {
    return __fdividef(1.0f, 1.0f + __expf(-x));
}
__device__ __forceinline__ float tanh_fast(float x) {
    return 1.0f - __fdividef(2.0f, __expf(2.0f * x) + 1.0f);
}

extern __shared__ float smem[];

__global__ void __launch_bounds__(NTHR, 1)
lstm_return_kernel(const float* __restrict__ x,
                   const float* __restrict__ Wih0, const float* __restrict__ Whh0,
                   const float* __restrict__ bih0, const float* __restrict__ bhh0,
                   const float* __restrict__ Wih1, const float* __restrict__ Whh1,
                   const float* __restrict__ bih1, const float* __restrict__ bhh1,
                   const float* __restrict__ W1,   const float* __restrict__ b1,
                   const float* __restrict__ W2,   const float* __restrict__ b2,
                   float* __restrict__ out)
{
    float* sW0 = smem;                 // [256][68]  Whh0
    float* sW1 = sW0 + G * SW0_S;      // [256][132] [Wih1|Whh1]
    float* zb0 = sW1 + G * SW1_S;      // [256][9]   layer-0 activated gates
    float* zb1 = zb0 + G * ZB_S;       // [256][9]   layer-1 activated gates
    float* in0 = zb1 + G * ZB_S;       // [8][96]    x(0:32) | h0(32:96)
    float* in1 = in0 + NB * 96;        // [8][128]   h0(0:64) | h1(64:128)

    const int tid   = threadIdx.x;
    const int j     = tid & 255;       // gate row within the owned layer
    const bool grpA = (tid < 256);     // A: layer 0, B: layer 1
    const int bbase = blockIdx.x * NB;

    // ---- stage weights into smem ----
    for (int i = tid; i < G * HDIM; i += NTHR) {
        int r = i >> 6, c = i & 63;
        sW0[r * SW0_S + c]        = Whh0[i];
        sW1[r * SW1_S + c]        = Wih1[i];
        sW1[r * SW1_S + HDIM + c] = Whh1[i];
    }
    for (int i = tid; i < NB * 96;  i += NTHR) in0[i] = 0.0f;
    for (int i = tid; i < NB * 128; i += NTHR) in1[i] = 0.0f;

    // ---- A: Wih0 row j in registers, packed f32x2 ----
    unsigned long long wxp[16];
#pragma unroll
    for (int k = 0; k < 16; k++) {
        float a = grpA ? Wih0[j * DIN + 2 * k]     : 0.0f;
        float b = grpA ? Wih0[j * DIN + 2 * k + 1] : 0.0f;
        wxp[k] = pack2(a, b);
    }

    const float bsum = grpA ? (bih0[j] + bhh0[j]) : (bih1[j] + bhh1[j]);
    const bool  row_is_tanh = ((j >> 6) == 2);   // g-gate rows

    // cell-state owner: every thread owns one (unit, batch) for each layer
    const int cu = tid & 63;
    const int cb = tid >> 6;          // 0..7
    float c0 = 0.f, c1 = 0.f;

    // x staging: A-threads -> (batch xb, channel xk)
    const int xb = (tid >> 5) & 7, xk = tid & 31;
    const float* xptr = x + ((size_t)(bbase + xb) * T_SEQ) * DIN + xk;
    float xreg = grpA ? xptr[0] : 0.0f;

    const float* w0row = sW0 + j * SW0_S;
    const float* w1row = sW1 + j * SW1_S;

    __syncthreads();
    // stage x(0), prefetch x(1)
    if (grpA) {
        in0[xb * 96 + xk] = xreg;
        xreg = xptr[DIN];
    }
    __syncthreads();

    // Skewed pipeline: iteration t computes gates0(t) [A] and gates1(t-1) [B]
    for (int t = 0; t <= T_SEQ; t++) {
        // ================= phase 1: both GEMV phases in parallel =================
        if (grpA) {
            if (t < T_SEQ) {
                unsigned long long acc[NB];
#pragma unroll
                for (int b = 0; b < NB; b++) acc[b] = pack2(bsum, 0.0f);
                // x part: register weights
#pragma unroll
                for (int kc = 0; kc < 8; kc++) {
                    const unsigned long long w0 = wxp[2 * kc], w1 = wxp[2 * kc + 1];
#pragma unroll
                    for (int b = 0; b < NB; b++) {
                        ulonglong2 iv = *(const ulonglong2*)(in0 + b * 96 + 4 * kc);
                        fma2(acc[b], w0, iv.x);
                        fma2(acc[b], w1, iv.y);
                    }
                }
                // h part: Whh0 from smem (pad-68 conflict-free)
#pragma unroll
                for (int kc = 0; kc < 16; kc++) {
                    ulonglong2 wv = *(const ulonglong2*)(w0row + 4 * kc);
#pragma unroll
                    for (int b = 0; b < NB; b++) {
                        ulonglong2 iv = *(const ulonglong2*)(in0 + b * 96 + 32 + 4 * kc);
                        fma2(acc[b], wv.x, iv.x);
                        fma2(acc[b], wv.y, iv.y);
                    }
                }
#pragma unroll
                for (int b = 0; b < NB; b++) {
                    float z = hsum2(acc[b]);
                    zb0[j * ZB_S + b] = row_is_tanh ? tanh_fast(z) : sigmoid_fast(z);
                }
            }
        } else {
            if (t > 0) {
                unsigned long long acc[NB];
#pragma unroll
                for (int b = 0; b < NB; b++) acc[b] = pack2(bsum, 0.0f);
#pragma unroll
                for (int kc = 0; kc < 32; kc++) {
                    ulonglong2 wv = *(const ulonglong2*)(w1row + 4 * kc);
#pragma unroll
                    for (int b = 0; b < NB; b++) {
                        ulonglong2 iv = *(const ulonglong2*)(in1 + b * 128 + 4 * kc);
                        fma2(acc[b], wv.x, iv.x);
                        fma2(acc[b], wv.y, iv.y);
                    }
                }
#pragma unroll
                for (int b = 0; b < NB; b++) {
                    float z = hsum2(acc[b]);
                    zb1[j * ZB_S + b] = row_is_tanh ? tanh_fast(z) : sigmoid_fast(z);
                }
            }
        }
        __syncthreads();                                  // (1)

        // ================= phase 2: cell updates (1 per thread per layer) ========
        if (t < T_SEQ) {
            const float* zc = zb0 + cu * ZB_S;
            float i_ = zc[0 * 64 * ZB_S + cb];
            float f_ = zc[1 * 64 * ZB_S + cb];
            float g_ = zc[2 * 64 * ZB_S + cb];
            float o_ = zc[3 * 64 * ZB_S + cb];
            c0 = f_ * c0 + i_ * g_;
            float h = o_ * tanh_fast(c0);
            in0[cb * 96 + 32 + cu] = h;   // for gates0(t+1)
            in1[cb * 128 + cu]     = h;   // for gates1(t)
        }
        if (t > 0) {
            const float* zc = zb1 + cu * ZB_S;
            float i_ = zc[0 * 64 * ZB_S + cb];
            float f_ = zc[1 * 64 * ZB_S + cb];
            float g_ = zc[2 * 64 * ZB_S + cb];
            float o_ = zc[3 * 64 * ZB_S + cb];
            c1 = f_ * c1 + i_ * g_;
            in1[cb * 128 + 64 + cu] = o_ * tanh_fast(c1);
        }
        // stage x(t+1), prefetch x(t+2)
        if (grpA && (t + 1 < T_SEQ)) {
            in0[xb * 96 + xk] = xreg;
            if (t + 2 < T_SEQ) xreg = xptr[(size_t)(t + 2) * DIN];
        }
        __syncthreads();                                  // (2)
    }

    // ===== head: out = relu(h1 @ W1^T + b1) @ W2^T + b2 =====
    if (tid < 256) {
        const int hb = tid >> 5;
        const int hu = tid & 31;
        const float* w1r = W1 + hu * HDIM;
        const float* hv  = in1 + hb * 128 + 64;
        float acc = b1[hu];
#pragma unroll
        for (int k = 0; k < HDIM; k++) acc += w1r[k] * hv[k];
        acc = fmaxf(acc, 0.0f) * W2[hu];
        zb0[hb * 32 + hu] = acc;
    }
    __syncthreads();
    if (tid < NB) {
        float s = b2[0];
#pragma unroll
        for (int u = 0; u < 32; u++) s += zb0[tid * 32 + u];
        out[bbase + tid] = s;
    }
}

extern "C" void kernel_launch(void* const* d_in, const int* in_sizes, int n_in,
                              void* d_out, int out_size) {
    (void)in_sizes; (void)n_in; (void)out_size;
    const float* x    = (const float*)d_in[0];
    const float* Wih0 = (const float*)d_in[1];
    const float* Whh0 = (const float*)d_in[2];
    const float* bih0 = (const float*)d_in[3];
    const float* bhh0 = (const float*)d_in[4];
    const float* Wih1 = (const float*)d_in[5];
    const float* Whh1 = (const float*)d_in[6];
    const float* bih1 = (const float*)d_in[7];
    const float* bhh1 = (const float*)d_in[8];
    const float* W1   = (const float*)d_in[9];
    const float* b1   = (const float*)d_in[10];
    const float* W2   = (const float*)d_in[11];
    const float* b2   = (const float*)d_in[12];
    float* out = (float*)d_out;

    const size_t smem_bytes = (size_t)SMEM_FLOATS * sizeof(float);
    cudaFuncSetAttribute(lstm_return_kernel,
                         cudaFuncAttributeMaxDynamicSharedMemorySize,
                         (int)smem_bytes);
    lstm_return_kernel<<<1024 / NB, NTHR, smem_bytes>>>(
        x, Wih0, Whh0, bih0, bhh0, Wih1, Whh1, bih1, bhh1,
        W1, b1, W2, b2, out);
}

// round 6
// speedup vs baseline: 1.4994x; 1.3119x over previous
#include <cuda_runtime.h>
#include <cuda_bf16.h>
#include <cstdint>

#define T_SEQ 512
#define DIN   32
#define HDIM  64
#define G     256     // 4*H gate rows
#define NB    8       // batches per CTA
#define NTHR  256     // A: warps 0-3 (layer 0), B: warps 4-7 (layer 1)
#define HALF  128
#define SW0_S 68      // Whh0 row stride: (68%32)=4, LDS.128 phase-conflict-free
#define SW1_S 132     // [Wih1|Whh1] row stride: (132%32)=4, conflict-free
#define ZB_S  9       // gate-exchange stride: coprime 32

// smem floats: sW0 17408 | sW1 33792 | zb0 2304 | zb1 2304 | in0 768 | in1 1024
#define SMEM_FLOATS (G*SW0_S + G*SW1_S + 2*(G*ZB_S) + NB*96 + NB*128)

__device__ __forceinline__ unsigned long long pack2(float lo, float hi) {
    unsigned long long r;
    asm("mov.b64 %0, {%1,%2};" : "=l"(r) : "f"(lo), "f"(hi));
    return r;
}
__device__ __forceinline__ void fma2(unsigned long long& d,
                                     unsigned long long a, unsigned long long b) {
    asm("fma.rn.f32x2 %0, %1, %2, %0;" : "+l"(d) : "l"(a), "l"(b));
}
__device__ __forceinline__ float hsum2(unsigned long long v) {
    float lo, hi;
    asm("mov.b64 {%0,%1}, %2;" : "=f"(lo), "=f"(hi) : "l"(v));
    return lo + hi;
}
__device__ __forceinline__ float sigmoid_fast(float x) {
    return __fdividef(1.0f, 1.0f + __expf(-x));
}
__device__ __forceinline__ float tanh_fast(float x) {
    return 1.0f - __fdividef(2.0f, __expf(2.0f * x) + 1.0f);
}

extern __shared__ float smem[];

__global__ void __launch_bounds__(NTHR, 1)
lstm_return_kernel(const float* __restrict__ x,
                   const float* __restrict__ Wih0, const float* __restrict__ Whh0,
                   const float* __restrict__ bih0, const float* __restrict__ bhh0,
                   const float* __restrict__ Wih1, const float* __restrict__ Whh1,
                   const float* __restrict__ bih1, const float* __restrict__ bhh1,
                   const float* __restrict__ W1,   const float* __restrict__ b1,
                   const float* __restrict__ W2,   const float* __restrict__ b2,
                   float* __restrict__ out)
{
    float* sW0 = smem;                 // [256][68]  Whh0
    float* sW1 = sW0 + G * SW0_S;      // [256][132] [Wih1|Whh1]
    float* zb0 = sW1 + G * SW1_S;      // [256][9]
    float* zb1 = zb0 + G * ZB_S;       // [256][9]
    float* in0 = zb1 + G * ZB_S;       // [8][96]   x | h0
    float* in1 = in0 + NB * 96;        // [8][128]  h0 | h1

    const int tid   = threadIdx.x;
    const bool grpA = (tid < HALF);
    const int jl    = tid & (HALF - 1);   // local row base: owns rows jl, jl+128
    const int bbase = blockIdx.x * NB;

    // ---- stage weights into smem ----
    for (int i = tid; i < G * HDIM; i += NTHR) {
        int r = i >> 6, c = i & 63;
        sW0[r * SW0_S + c]        = Whh0[i];
        sW1[r * SW1_S + c]        = Wih1[i];
        sW1[r * SW1_S + HDIM + c] = Whh1[i];
    }
    for (int i = tid; i < NB * 96;  i += NTHR) in0[i] = 0.0f;
    for (int i = tid; i < NB * 128; i += NTHR) in1[i] = 0.0f;

    // ---- A: Wih0 rows jl and jl+128 in registers, packed f32x2 ----
    unsigned long long wx0[16], wx1[16];
#pragma unroll
    for (int k = 0; k < 16; k++) {
        int r0 = jl * DIN + 2 * k, r1 = (jl + HALF) * DIN + 2 * k;
        wx0[k] = grpA ? pack2(Wih0[r0], Wih0[r0 + 1]) : 0ull;
        wx1[k] = grpA ? pack2(Wih0[r1], Wih0[r1 + 1]) : 0ull;
    }

    // biases for the two owned rows
    float bsA, bsB;
    if (grpA) { bsA = bih0[jl] + bhh0[jl]; bsB = bih0[jl + HALF] + bhh0[jl + HALF]; }
    else      { bsA = bih1[jl] + bhh1[jl]; bsB = bih1[jl + HALF] + bhh1[jl + HALF]; }
    // row jl (gates i/f): always sigmoid. row jl+128: tanh iff jl<64 (g), else o.
    const bool row2_tanh = (jl < 64);

    // cell ownership within group: u = jl&63, batches bgrp*4 .. bgrp*4+3
    const int cu  = jl & 63;
    const int cbg = (jl >> 6) * 4;
    float cst[4];
#pragma unroll
    for (int q = 0; q < 4; q++) cst[q] = 0.0f;

    // x staging: all 256 threads, (batch xb, channel xk)
    const int xb = tid >> 5, xk = tid & 31;
    const float* xptr = x + ((size_t)(bbase + xb) * T_SEQ) * DIN + xk;
    float xreg = xptr[0];

    const float* w0rA = sW0 + jl * SW0_S;
    const float* w0rB = sW0 + (jl + HALF) * SW0_S;
    const float* w1rA = sW1 + jl * SW1_S;
    const float* w1rB = sW1 + (jl + HALF) * SW1_S;

    __syncthreads();
    // stage x(0), prefetch x(1)
    in0[xb * 96 + xk] = xreg;
    xreg = xptr[DIN];
    __syncthreads();

    // skewed pipeline: iter t = gates0(t) [A] || gates1(t-1) [B]
    for (int t = 0; t <= T_SEQ; t++) {
        if (grpA) {
            if (t < T_SEQ) {
                unsigned long long a0[NB], a1[NB];
#pragma unroll
                for (int b = 0; b < NB; b++) { a0[b] = pack2(bsA, 0.f); a1[b] = pack2(bsB, 0.f); }
                // x part: register weights, one input load feeds both rows
#pragma unroll
                for (int kc = 0; kc < 8; kc++) {
                    const unsigned long long u0 = wx0[2*kc], u1 = wx0[2*kc+1];
                    const unsigned long long v0 = wx1[2*kc], v1 = wx1[2*kc+1];
#pragma unroll
                    for (int b = 0; b < NB; b++) {
                        ulonglong2 iv = *(const ulonglong2*)(in0 + b * 96 + 4 * kc);
                        fma2(a0[b], u0, iv.x); fma2(a0[b], u1, iv.y);
                        fma2(a1[b], v0, iv.x); fma2(a1[b], v1, iv.y);
                    }
                }
                // h part: two weight rows from smem, shared input load
#pragma unroll
                for (int kc = 0; kc < 16; kc++) {
                    ulonglong2 wvA = *(const ulonglong2*)(w0rA + 4 * kc);
                    ulonglong2 wvB = *(const ulonglong2*)(w0rB + 4 * kc);
#pragma unroll
                    for (int b = 0; b < NB; b++) {
                        ulonglong2 iv = *(const ulonglong2*)(in0 + b * 96 + 32 + 4 * kc);
                        fma2(a0[b], wvA.x, iv.x); fma2(a0[b], wvA.y, iv.y);
                        fma2(a1[b], wvB.x, iv.x); fma2(a1[b], wvB.y, iv.y);
                    }
                }
#pragma unroll
                for (int b = 0; b < NB; b++) {
                    float z0 = hsum2(a0[b]);
                    float z1 = hsum2(a1[b]);
                    zb0[jl * ZB_S + b]          = sigmoid_fast(z0);
                    zb0[(jl + HALF) * ZB_S + b] = row2_tanh ? tanh_fast(z1) : sigmoid_fast(z1);
                }
            }
        } else {
            if (t > 0) {
                unsigned long long a0[NB], a1[NB];
#pragma unroll
                for (int b = 0; b < NB; b++) { a0[b] = pack2(bsA, 0.f); a1[b] = pack2(bsB, 0.f); }
#pragma unroll
                for (int kc = 0; kc < 32; kc++) {
                    ulonglong2 wvA = *(const ulonglong2*)(w1rA + 4 * kc);
                    ulonglong2 wvB = *(const ulonglong2*)(w1rB + 4 * kc);
#pragma unroll
                    for (int b = 0; b < NB; b++) {
                        ulonglong2 iv = *(const ulonglong2*)(in1 + b * 128 + 4 * kc);
                        fma2(a0[b], wvA.x, iv.x); fma2(a0[b], wvA.y, iv.y);
                        fma2(a1[b], wvB.x, iv.x); fma2(a1[b], wvB.y, iv.y);
                    }
                }
#pragma unroll
                for (int b = 0; b < NB; b++) {
                    float z0 = hsum2(a0[b]);
                    float z1 = hsum2(a1[b]);
                    zb1[jl * ZB_S + b]          = sigmoid_fast(z0);
                    zb1[(jl + HALF) * ZB_S + b] = row2_tanh ? tanh_fast(z1) : sigmoid_fast(z1);
                }
            }
        }
        __syncthreads();                                  // (1) gates visible

        // ===== phase 2: cell updates, 4 cells per thread within own group =====
        if (grpA) {
            if (t < T_SEQ) {
                const float* zc = zb0 + cu * ZB_S;
#pragma unroll
                for (int q = 0; q < 4; q++) {
                    int b = cbg + q;
                    float i_ = zc[0 * 64 * ZB_S + b];
                    float f_ = zc[1 * 64 * ZB_S + b];
                    float g_ = zc[2 * 64 * ZB_S + b];
                    float o_ = zc[3 * 64 * ZB_S + b];
                    cst[q] = f_ * cst[q] + i_ * g_;
                    float h = o_ * tanh_fast(cst[q]);
                    in0[b * 96 + 32 + cu] = h;   // for gates0(t+1)
                    in1[b * 128 + cu]     = h;   // for gates1(t)
                }
            }
        } else {
            if (t > 0) {
                const float* zc = zb1 + cu * ZB_S;
#pragma unroll
                for (int q = 0; q < 4; q++) {
                    int b = cbg + q;
                    float i_ = zc[0 * 64 * ZB_S + b];
                    float f_ = zc[1 * 64 * ZB_S + b];
                    float g_ = zc[2 * 64 * ZB_S + b];
                    float o_ = zc[3 * 64 * ZB_S + b];
                    cst[q] = f_ * cst[q] + i_ * g_;
                    in1[b * 128 + 64 + cu] = o_ * tanh_fast(cst[q]);
                }
            }
        }
        // stage x(t+1), prefetch x(t+2)
        if (t + 1 < T_SEQ) {
            in0[xb * 96 + xk] = xreg;
            if (t + 2 < T_SEQ) xreg = xptr[(size_t)(t + 2) * DIN];
        }
        __syncthreads();                                  // (2)
    }

    // ===== head: out = relu(h1 @ W1^T + b1) @ W2^T + b2 =====
    {
        const int hb = tid >> 5;
        const int hu = tid & 31;
        const float* w1r = W1 + hu * HDIM;
        const float* hv  = in1 + hb * 128 + 64;
        float acc = b1[hu];
#pragma unroll
        for (int k = 0; k < HDIM; k++) acc += w1r[k] * hv[k];
        acc = fmaxf(acc, 0.0f) * W2[hu];
        zb0[hb * 32 + hu] = acc;
    }
    __syncthreads();
    if (tid < NB) {
        float s = b2[0];
#pragma unroll
        for (int u = 0; u < 32; u++) s += zb0[tid * 32 + u];
        out[bbase + tid] = s;
    }
}

extern "C" void kernel_launch(void* const* d_in, const int* in_sizes, int n_in,
                              void* d_out, int out_size) {
    (void)in_sizes; (void)n_in; (void)out_size;
    const float* x    = (const float*)d_in[0];
    const float* Wih0 = (const float*)d_in[1];
    const float* Whh0 = (const float*)d_in[2];
    const float* bih0 = (const float*)d_in[3];
    const float* bhh0 = (const float*)d_in[4];
    const float* Wih1 = (const float*)d_in[5];
    const float* Whh1 = (const float*)d_in[6];
    const float* bih1 = (const float*)d_in[7];
    const float* bhh1 = (const float*)d_in[8];
    const float* W1   = (const float*)d_in[9];
    const float* b1   = (const float*)d_in[10];
    const float* W2   = (const float*)d_in[11];
    const float* b2   = (const float*)d_in[12];
    float* out = (float*)d_out;

    const size_t smem_bytes = (size_t)SMEM_FLOATS * sizeof(float);
    cudaFuncSetAttribute(lstm_return_kernel,
                         cudaFuncAttributeMaxDynamicSharedMemorySize,
                         (int)smem_bytes);
    lstm_return_kernel<<<1024 / NB, NTHR, smem_bytes>>>(
        x, Wih0, Whh0, bih0, bhh0, Wih1, Whh1, bih1, bhh1,
        W1, b1, W2, b2, out);
}

// round 7
// speedup vs baseline: 1.6363x; 1.0913x over previous
#include <cuda_runtime.h>
#include <cuda_bf16.h>
#include <cstdint>

#define T_SEQ 512
#define DIN   32
#define HDIM  64
#define G     256     // 4*H gate rows
#define NB    8       // batches per CTA
#define NTHR  256     // A: warps 0-3 (layer 0), B: warps 4-7 (layer 1)
#define HALF  128
#define SW0_S 68      // Whh0 row stride: 68%32=4 -> conflict-free LDS.128
#define SW1_S 132     // [Wih1|Whh1] row stride: 132%32=4 -> conflict-free
#define ZB_S  8       // gate rows stored as 2x STS.128

// smem floats: sW0 17408 | sW1 33792 | zb0 2048 | zb1 2048 | in0 768
//              h0buf 2*512=1024 | h1buf 512      total 57600 fl = 230400 B
#define SMEM_FLOATS (G*SW0_S + G*SW1_S + 2*(G*ZB_S) + NB*96 + 2*NB*64 + NB*64)

__device__ __forceinline__ unsigned long long pack2(float lo, float hi) {
    unsigned long long r;
    asm("mov.b64 %0, {%1,%2};" : "=l"(r) : "f"(lo), "f"(hi));
    return r;
}
__device__ __forceinline__ void fma2(unsigned long long& d,
                                     unsigned long long a, unsigned long long b) {
    asm("fma.rn.f32x2 %0, %1, %2, %0;" : "+l"(d) : "l"(a), "l"(b));
}
__device__ __forceinline__ float hsum2(unsigned long long v) {
    float lo, hi;
    asm("mov.b64 {%0,%1}, %2;" : "=f"(lo), "=f"(hi) : "l"(v));
    return lo + hi;
}
__device__ __forceinline__ float sigmoid_fast(float x) {
    return __fdividef(1.0f, 1.0f + __expf(-x));
}
__device__ __forceinline__ float tanh_fast(float x) {
    return 1.0f - __fdividef(2.0f, __expf(2.0f * x) + 1.0f);
}
__device__ __forceinline__ void bar_sync(int id, int cnt) {
    asm volatile("bar.sync %0, %1;" :: "r"(id), "r"(cnt) : "memory");
}
__device__ __forceinline__ void bar_arrive(int id, int cnt) {
    asm volatile("bar.arrive %0, %1;" :: "r"(id), "r"(cnt) : "memory");
}

extern __shared__ float smem[];

__global__ void __launch_bounds__(NTHR, 1)
lstm_return_kernel(const float* __restrict__ x,
                   const float* __restrict__ Wih0, const float* __restrict__ Whh0,
                   const float* __restrict__ bih0, const float* __restrict__ bhh0,
                   const float* __restrict__ Wih1, const float* __restrict__ Whh1,
                   const float* __restrict__ bih1, const float* __restrict__ bhh1,
                   const float* __restrict__ W1,   const float* __restrict__ b1,
                   const float* __restrict__ W2,   const float* __restrict__ b2,
                   float* __restrict__ out)
{
    float* sW0   = smem;                  // [256][68]  Whh0
    float* sW1   = sW0 + G * SW0_S;       // [256][132] [Wih1|Whh1]
    float* zb0   = sW1 + G * SW1_S;       // [256][8]   L0 gates
    float* zb1   = zb0 + G * ZB_S;        // [256][8]   L1 gates
    float* in0   = zb1 + G * ZB_S;        // [8][96]    x | h0  (A-private)
    float* h0buf = in0 + NB * 96;         // [2][8][64] A->B hand-off
    float* h1buf = h0buf + 2 * NB * 64;   // [8][64]    B-private h1

    const int tid   = threadIdx.x;
    const bool grpA = (tid < HALF);
    const int jl    = tid & (HALF - 1);   // owns rows jl, jl+128 of its layer
    const int bbase = blockIdx.x * NB;

    // ---- stage weights into smem ----
    for (int i = tid; i < G * HDIM; i += NTHR) {
        int r = i >> 6, c = i & 63;
        sW0[r * SW0_S + c]        = Whh0[i];
        sW1[r * SW1_S + c]        = Wih1[i];
        sW1[r * SW1_S + HDIM + c] = Whh1[i];
    }
    for (int i = tid; i < NB * 96; i += NTHR) in0[i] = 0.0f;
    for (int i = tid; i < 3 * NB * 64; i += NTHR) h0buf[i] = 0.0f; // h0buf + h1buf
    // ---- A: Wih0 rows jl, jl+128 in registers ----
    unsigned long long wx0[16], wx1[16];
#pragma unroll
    for (int k = 0; k < 16; k++) {
        int r0 = jl * DIN + 2 * k, r1 = (jl + HALF) * DIN + 2 * k;
        wx0[k] = grpA ? pack2(Wih0[r0], Wih0[r0 + 1]) : 0ull;
        wx1[k] = grpA ? pack2(Wih0[r1], Wih0[r1 + 1]) : 0ull;
    }
    float bsA, bsB;
    if (grpA) { bsA = bih0[jl] + bhh0[jl]; bsB = bih0[jl + HALF] + bhh0[jl + HALF]; }
    else      { bsA = bih1[jl] + bhh1[jl]; bsB = bih1[jl + HALF] + bhh1[jl + HALF]; }
    const bool row2_tanh = (jl < 64);     // second row is g-gate iff jl<64

    const int cu  = jl & 63;              // cell unit
    const int cbg = (jl >> 6) * 4;        // first of 4 owned batches
    float cst[4] = {0.f, 0.f, 0.f, 0.f};

    // x staging (A only): thread -> (batch xb, channels xc, xc+1)
    const int xb = tid >> 4, xc = (tid & 15) * 2;
    const float* xptr = x + ((size_t)(bbase + (xb & 7)) * T_SEQ) * DIN + xc;
    float2 xcur = make_float2(0.f, 0.f);

    const float* w0rA = sW0 + jl * SW0_S;
    const float* w0rB = sW0 + (jl + HALF) * SW0_S;
    const float* w1rA = sW1 + jl * SW1_S;
    const float* w1rB = sW1 + (jl + HALF) * SW1_S;

    if (grpA) {
        // stage x(0), prefetch x(1)
        float2 v0 = *(const float2*)(xptr);
        *(float2*)(in0 + xb * 96 + xc) = v0;
        xcur = *(const float2*)(xptr + DIN);
    }
    __syncthreads();

    if (grpA) {
        // ============================ GROUP A: layer 0 ============================
        for (int t = 0; t < T_SEQ; t++) {
            const int p = t & 1;
            // ---- gates0(t): x(t), h0(t-1) from in0 ----
            unsigned long long a0[NB], a1[NB];
#pragma unroll
            for (int b = 0; b < NB; b++) { a0[b] = pack2(bsA, 0.f); a1[b] = pack2(bsB, 0.f); }
#pragma unroll
            for (int kc = 0; kc < 8; kc++) {
                const unsigned long long u0 = wx0[2*kc], u1 = wx0[2*kc+1];
                const unsigned long long v0 = wx1[2*kc], v1 = wx1[2*kc+1];
#pragma unroll
                for (int b = 0; b < NB; b++) {
                    ulonglong2 iv = *(const ulonglong2*)(in0 + b * 96 + 4 * kc);
                    fma2(a0[b], u0, iv.x); fma2(a0[b], u1, iv.y);
                    fma2(a1[b], v0, iv.x); fma2(a1[b], v1, iv.y);
                }
            }
#pragma unroll
            for (int kc = 0; kc < 16; kc++) {
                ulonglong2 wvA = *(const ulonglong2*)(w0rA + 4 * kc);
                ulonglong2 wvB = *(const ulonglong2*)(w0rB + 4 * kc);
#pragma unroll
                for (int b = 0; b < NB; b++) {
                    ulonglong2 iv = *(const ulonglong2*)(in0 + b * 96 + 32 + 4 * kc);
                    fma2(a0[b], wvA.x, iv.x); fma2(a0[b], wvA.y, iv.y);
                    fma2(a1[b], wvB.x, iv.x); fma2(a1[b], wvB.y, iv.y);
                }
            }
            float r0[NB], r1[NB];
#pragma unroll
            for (int b = 0; b < NB; b++) {
                r0[b] = sigmoid_fast(hsum2(a0[b]));
                float z1 = hsum2(a1[b]);
                r1[b] = row2_tanh ? tanh_fast(z1) : sigmoid_fast(z1);
            }
            *(float4*)(zb0 + jl * ZB_S)              = make_float4(r0[0], r0[1], r0[2], r0[3]);
            *(float4*)(zb0 + jl * ZB_S + 4)          = make_float4(r0[4], r0[5], r0[6], r0[7]);
            *(float4*)(zb0 + (jl + HALF) * ZB_S)     = make_float4(r1[0], r1[1], r1[2], r1[3]);
            *(float4*)(zb0 + (jl + HALF) * ZB_S + 4) = make_float4(r1[4], r1[5], r1[6], r1[7]);

            bar_sync(5, HALF);                       // zb0 visible within A
            if (t >= 2) bar_sync(3 + p, NTHR);       // h0buf[p] free (B consumed t-2)

            // ---- cell0(t): 4 cells per thread ----
            {
                const float* zc = zb0 + cu * ZB_S;
                float* hb = h0buf + p * (NB * 64);
#pragma unroll
                for (int q = 0; q < 4; q++) {
                    int b = cbg + q;
                    float i_ = zc[0 * 64 * ZB_S + b];
                    float f_ = zc[1 * 64 * ZB_S + b];
                    float g_ = zc[2 * 64 * ZB_S + b];
                    float o_ = zc[3 * 64 * ZB_S + b];
                    cst[q] = f_ * cst[q] + i_ * g_;
                    float h = o_ * tanh_fast(cst[q]);
                    in0[b * 96 + 32 + cu] = h;       // for gates0(t+1)
                    hb[b * 64 + cu]       = h;       // for B's gates1(t)
                }
            }
            // stage x(t+1), prefetch x(t+2)
            if (t + 1 < T_SEQ) {
                *(float2*)(in0 + xb * 96 + xc) = xcur;
                if (t + 2 < T_SEQ) xcur = *(const float2*)(xptr + (size_t)(t + 2) * DIN);
            }
            bar_arrive(1 + p, NTHR);                 // h0(t) ready for B
            bar_sync(6, HALF);                       // in0 writes visible within A
        }
    } else {
        // ============================ GROUP B: layer 1 ============================
        for (int t = 0; t < T_SEQ; t++) {
            const int p = t & 1;
            bar_sync(1 + p, NTHR);                   // wait h0(t); also B rendezvous
            const float* h0p = h0buf + p * (NB * 64);

            unsigned long long a0[NB], a1[NB];
#pragma unroll
            for (int b = 0; b < NB; b++) { a0[b] = pack2(bsA, 0.f); a1[b] = pack2(bsB, 0.f); }
#pragma unroll
            for (int kc = 0; kc < 16; kc++) {        // h0 part (Wih1)
                ulonglong2 wvA = *(const ulonglong2*)(w1rA + 4 * kc);
                ulonglong2 wvB = *(const ulonglong2*)(w1rB + 4 * kc);
#pragma unroll
                for (int b = 0; b < NB; b++) {
                    ulonglong2 iv = *(const ulonglong2*)(h0p + b * 64 + 4 * kc);
                    fma2(a0[b], wvA.x, iv.x); fma2(a0[b], wvA.y, iv.y);
                    fma2(a1[b], wvB.x, iv.x); fma2(a1[b], wvB.y, iv.y);
                }
            }
            bar_arrive(3 + p, NTHR);                 // h0buf[p] consumed
#pragma unroll
            for (int kc = 0; kc < 16; kc++) {        // h1 part (Whh1)
                ulonglong2 wvA = *(const ulonglong2*)(w1rA + 64 + 4 * kc);
                ulonglong2 wvB = *(const ulonglong2*)(w1rB + 64 + 4 * kc);
#pragma unroll
                for (int b = 0; b < NB; b++) {
                    ulonglong2 iv = *(const ulonglong2*)(h1buf + b * 64 + 4 * kc);
                    fma2(a0[b], wvA.x, iv.x); fma2(a0[b], wvA.y, iv.y);
                    fma2(a1[b], wvB.x, iv.x); fma2(a1[b], wvB.y, iv.y);
                }
            }
            float r0[NB], r1[NB];
#pragma unroll
            for (int b = 0; b < NB; b++) {
                r0[b] = sigmoid_fast(hsum2(a0[b]));
                float z1 = hsum2(a1[b]);
                r1[b] = row2_tanh ? tanh_fast(z1) : sigmoid_fast(z1);
            }
            *(float4*)(zb1 + jl * ZB_S)              = make_float4(r0[0], r0[1], r0[2], r0[3]);
            *(float4*)(zb1 + jl * ZB_S + 4)          = make_float4(r0[4], r0[5], r0[6], r0[7]);
            *(float4*)(zb1 + (jl + HALF) * ZB_S)     = make_float4(r1[0], r1[1], r1[2], r1[3]);
            *(float4*)(zb1 + (jl + HALF) * ZB_S + 4) = make_float4(r1[4], r1[5], r1[6], r1[7]);

            bar_sync(7, HALF);                       // zb1 visible within B
            // ---- cell1(t) ----
            {
                const float* zc = zb1 + cu * ZB_S;
#pragma unroll
                for (int q = 0; q < 4; q++) {
                    int b = cbg + q;
                    float i_ = zc[0 * 64 * ZB_S + b];
                    float f_ = zc[1 * 64 * ZB_S + b];
                    float g_ = zc[2 * 64 * ZB_S + b];
                    float o_ = zc[3 * 64 * ZB_S + b];
                    cst[q] = f_ * cst[q] + i_ * g_;
                    h1buf[b * 64 + cu] = o_ * tanh_fast(cst[q]);
                }
            }
            // h1buf write->read ordering for t+1 provided by bar.sync(1+p') rendezvous
        }
    }

    __syncthreads();   // final h1 visible to all

    // ===== head: out = relu(h1 @ W1^T + b1) @ W2^T + b2 =====
    {
        const int hb = tid >> 5;
        const int hu = tid & 31;
        const float* w1r = W1 + hu * HDIM;
        const float* hv  = h1buf + hb * 64;
        float acc = b1[hu];
#pragma unroll
        for (int k = 0; k < HDIM; k++) acc += w1r[k] * hv[k];
        acc = fmaxf(acc, 0.0f) * W2[hu];
        zb0[hb * 32 + hu] = acc;
    }
    __syncthreads();
    if (tid < NB) {
        float s = b2[0];
#pragma unroll
        for (int u = 0; u < 32; u++) s += zb0[tid * 32 + u];
        out[bbase + tid] = s;
    }
}

extern "C" void kernel_launch(void* const* d_in, const int* in_sizes, int n_in,
                              void* d_out, int out_size) {
    (void)in_sizes; (void)n_in; (void)out_size;
    const float* x    = (const float*)d_in[0];
    const float* Wih0 = (const float*)d_in[1];
    const float* Whh0 = (const float*)d_in[2];
    const float* bih0 = (const float*)d_in[3];
    const float* bhh0 = (const float*)d_in[4];
    const float* Wih1 = (const float*)d_in[5];
    const float* Whh1 = (const float*)d_in[6];
    const float* bih1 = (const float*)d_in[7];
    const float* bhh1 = (const float*)d_in[8];
    const float* W1   = (const float*)d_in[9];
    const float* b1   = (const float*)d_in[10];
    const float* W2   = (const float*)d_in[11];
    const float* b2   = (const float*)d_in[12];
    float* out = (float*)d_out;

    const size_t smem_bytes = (size_t)SMEM_FLOATS * sizeof(float);
    cudaFuncSetAttribute(lstm_return_kernel,
                         cudaFuncAttributeMaxDynamicSharedMemorySize,
                         (int)smem_bytes);
    lstm_return_kernel<<<1024 / NB, NTHR, smem_bytes>>>(
        x, Wih0, Whh0, bih0, bhh0, Wih1, Whh1, bih1, bhh1,
        W1, b1, W2, b2, out);
}